// round 2
// baseline (speedup 1.0000x reference)
#include <cuda_runtime.h>
#include <cuda_fp16.h>
#include <cstdint>

#define IN_FEATS   128
#define HIDDEN     128
#define KDIM       256           // 2 * IN_FEATS
#define M_TILE     128           // edges per CTA
#define MAX_NODES  100000
#define NUM_KSTEP  16            // KDIM / 16

// Persistent scratch (allocation-free rule: __device__ globals)
__device__ __align__(16) __half g_h16[MAX_NODES * IN_FEATS];   // fp16 copy of h
__device__ __align__(16) __half g_w1h[HIDDEN * KDIM];          // fp16 W1, row-major [n][k]

// ---------------- SMEM layout ----------------
// Padded rows: 256 halfs + 8 pad = 264 halfs = 528 B stride (16B aligned,
// ldmatrix conflict-free: rows advance 4 banks, 8 rows x 16B = all 32 banks).
#define A_STRIDE_H 264
#define TILE_BYTES (128 * A_STRIDE_H * 2)     // 67584
#define SM_A     0
#define SM_B     (SM_A + TILE_BYTES)
#define SM_B1    (SM_B + TILE_BYTES)          // 128 f32
#define SM_W2    (SM_B1 + 512)                // 128 f32
#define SM_PART  (SM_W2 + 512)                // 128 f32 partials
#define SM_IDX   (SM_PART + 512)              // 256 int32
#define SM_TOTAL (SM_IDX + 1024)              // 137216 B

__device__ __forceinline__ uint32_t smem_u32(const void* p) {
    uint32_t a;
    asm("{ .reg .u64 t; cvta.to.shared.u64 t, %1; cvt.u32.u64 %0, t; }" : "=r"(a) : "l"(p));
    return a;
}

#define LDMATRIX_X4(r0, r1, r2, r3, addr) \
    asm volatile("ldmatrix.sync.aligned.m8n8.x4.shared.b16 {%0,%1,%2,%3}, [%4];" \
                 : "=r"(r0), "=r"(r1), "=r"(r2), "=r"(r3) : "r"(addr))

#define MMA16816(c0, c1, c2, c3, a0, a1, a2, a3, b0, b1) \
    asm volatile("mma.sync.aligned.m16n8k16.row.col.f32.f16.f16.f32 " \
                 "{%0,%1,%2,%3}, {%4,%5,%6,%7}, {%8,%9}, {%0,%1,%2,%3};" \
                 : "+f"(c0), "+f"(c1), "+f"(c2), "+f"(c3) \
                 : "r"(a0), "r"(a1), "r"(a2), "r"(a3), "r"(b0), "r"(b1))

// ---------------- Prep kernels ----------------
__global__ void conv_h_kernel(const float* __restrict__ h, int n4) {
    int i = blockIdx.x * blockDim.x + threadIdx.x;
    if (i < n4) {
        float4 v = reinterpret_cast<const float4*>(h)[i];
        __half2* o2 = reinterpret_cast<__half2*>(g_h16);
        o2[i * 2 + 0] = __floats2half2_rn(v.x, v.y);
        o2[i * 2 + 1] = __floats2half2_rn(v.z, v.w);
    }
}

__global__ void conv_w1_kernel(const float* __restrict__ W1, int n4) {
    int i = blockIdx.x * blockDim.x + threadIdx.x;
    if (i < n4) {
        float4 v = reinterpret_cast<const float4*>(W1)[i];
        __half2* o2 = reinterpret_cast<__half2*>(g_w1h);
        o2[i * 2 + 0] = __floats2half2_rn(v.x, v.y);
        o2[i * 2 + 1] = __floats2half2_rn(v.z, v.w);
    }
}

// ---------------- Main fused kernel ----------------
// CTA: 256 threads = 8 warps in 4(M) x 2(N) grid.
// Warp (wm, wn): rows wm*32..+31, cols wn*64..+63 of D[128 edges, 128 hidden].
__global__ void __launch_bounds__(256, 1)
edge_mlp_kernel(const int* __restrict__ src, const int* __restrict__ dst,
                const float* __restrict__ b1, const float* __restrict__ W2,
                const float* __restrict__ b2, float* __restrict__ out, int E)
{
    extern __shared__ char smem[];
    const int tid = threadIdx.x;
    const int wid = tid >> 5;
    const int lid = tid & 31;
    const uint32_t sb = smem_u32(smem);
    const int tile = blockIdx.x;

    // Stage bias/W2 and edge indices
    if (tid < 128) {
        reinterpret_cast<float*>(smem + SM_B1)[tid] = b1[tid];
        reinterpret_cast<float*>(smem + SM_W2)[tid] = W2[tid];
        int e = tile * M_TILE + tid;
        int s = 0, d = 0;
        if (e < E) { s = src[e]; d = dst[e]; }
        reinterpret_cast<int*>(smem + SM_IDX)[2 * tid + 0] = s;
        reinterpret_cast<int*>(smem + SM_IDX)[2 * tid + 1] = d;
    }
    __syncthreads();

    // ---- Load B (W1 fp16, [128 n][256 k]) into padded SMEM rows ----
    {
        const int j  = tid & 31;          // 16B chunk (32 per 512B row)
        const int rg = tid >> 5;
        #pragma unroll
        for (int g = 0; g < 16; g++) {
            int n = g * 8 + rg;
            const uint4* rowp = reinterpret_cast<const uint4*>(g_w1h + n * KDIM);
            *reinterpret_cast<uint4*>(smem + SM_B + n * (A_STRIDE_H * 2) + j * 16) = rowp[j];
        }
    }

    // ---- Gather A: 128 edges x (src 128 | dst 128) halfs, padded rows ----
    {
        const int* idxsh = reinterpret_cast<const int*>(smem + SM_IDX);
        const int j  = tid & 31;          // 16B chunk within 512B logical row
        const int rg = tid >> 5;
        #pragma unroll
        for (int g = 0; g < 16; g++) {
            int r  = g * 8 + rg;          // edge row 0..127
            int hf = j >> 4;              // 0 = src half, 1 = dst half
            int idx = idxsh[2 * r + hf];
            const uint4* rowp = reinterpret_cast<const uint4*>(g_h16 + (size_t)idx * IN_FEATS);
            *reinterpret_cast<uint4*>(smem + SM_A + r * (A_STRIDE_H * 2) + j * 16) = rowp[j & 15];
        }
    }
    __syncthreads();

    // ---- GEMM: D = A @ W1^T via mma.sync m16n8k16 ----
    const int wm = wid & 3;               // M block (32 rows)
    const int wn = wid >> 2;              // N half (64 cols)
    const int lr = lid & 15;              // ldmatrix row-within-16
    const int lc = (lid >> 4) * 8;        // ldmatrix k-subblock (+0 / +8 halfs)

    float acc[2][8][4];
    #pragma unroll
    for (int mt = 0; mt < 2; mt++)
        #pragma unroll
        for (int nt = 0; nt < 8; nt++)
            #pragma unroll
            for (int c = 0; c < 4; c++) acc[mt][nt][c] = 0.f;

    const uint32_t a_lane = sb + SM_A + (uint32_t)(wm * 32 + lr) * (A_STRIDE_H * 2) + (uint32_t)lc * 2;
    const uint32_t b_lane = sb + SM_B + (uint32_t)(wn * 64 + lr) * (A_STRIDE_H * 2) + (uint32_t)lc * 2;

    #pragma unroll
    for (int ks = 0; ks < NUM_KSTEP; ks++) {
        const uint32_t koff = (uint32_t)(ks * 16) * 2;
        uint32_t a0[4], a1[4];
        LDMATRIX_X4(a0[0], a0[1], a0[2], a0[3], a_lane + koff);
        LDMATRIX_X4(a1[0], a1[1], a1[2], a1[3], a_lane + (uint32_t)(16 * A_STRIDE_H * 2) + koff);
        uint32_t bf[4][4];                // [ntp][reg]
        #pragma unroll
        for (int ntp = 0; ntp < 4; ntp++) {
            LDMATRIX_X4(bf[ntp][0], bf[ntp][1], bf[ntp][2], bf[ntp][3],
                        b_lane + (uint32_t)(ntp * 16 * A_STRIDE_H * 2) + koff);
        }
        // bf[ntp]: r0 = (nt=2*ntp, k-low), r1 = (nt=2*ntp+1, k-low),
        //          r2 = (nt=2*ntp, k-high), r3 = (nt=2*ntp+1, k-high)
        #pragma unroll
        for (int ntp = 0; ntp < 4; ntp++) {
            MMA16816(acc[0][2*ntp][0], acc[0][2*ntp][1], acc[0][2*ntp][2], acc[0][2*ntp][3],
                     a0[0], a0[1], a0[2], a0[3], bf[ntp][0], bf[ntp][2]);
            MMA16816(acc[0][2*ntp+1][0], acc[0][2*ntp+1][1], acc[0][2*ntp+1][2], acc[0][2*ntp+1][3],
                     a0[0], a0[1], a0[2], a0[3], bf[ntp][1], bf[ntp][3]);
            MMA16816(acc[1][2*ntp][0], acc[1][2*ntp][1], acc[1][2*ntp][2], acc[1][2*ntp][3],
                     a1[0], a1[1], a1[2], a1[3], bf[ntp][0], bf[ntp][2]);
            MMA16816(acc[1][2*ntp+1][0], acc[1][2*ntp+1][1], acc[1][2*ntp+1][2], acc[1][2*ntp+1][3],
                     a1[0], a1[1], a1[2], a1[3], bf[ntp][1], bf[ntp][3]);
        }
    }

    // ---- Fused epilogue: +b1, ReLU, dot W2, reduce, sigmoid ----
    const int g   = lid >> 2;
    const int tig = lid & 3;
    const float* b1s = reinterpret_cast<const float*>(smem + SM_B1);
    const float* w2s = reinterpret_cast<const float*>(smem + SM_W2);

    float rowsum[4];                      // [mt*2 + half] -> row wm*32 + mt*16 + g + half*8
    #pragma unroll
    for (int mt = 0; mt < 2; mt++) {
        #pragma unroll
        for (int hh = 0; hh < 2; hh++) {
            float s = 0.f;
            #pragma unroll
            for (int nt = 0; nt < 8; nt++) {
                int col = wn * 64 + nt * 8 + tig * 2;
                float v0 = fmaxf(acc[mt][nt][hh * 2 + 0] + b1s[col], 0.f);
                float v1 = fmaxf(acc[mt][nt][hh * 2 + 1] + b1s[col + 1], 0.f);
                s = fmaf(v0, w2s[col], s);
                s = fmaf(v1, w2s[col + 1], s);
            }
            rowsum[mt * 2 + hh] = s;
        }
    }
    #pragma unroll
    for (int i = 0; i < 4; i++) {
        rowsum[i] += __shfl_xor_sync(0xFFFFFFFF, rowsum[i], 1);
        rowsum[i] += __shfl_xor_sync(0xFFFFFFFF, rowsum[i], 2);
    }

    float* part = reinterpret_cast<float*>(smem + SM_PART);
    if (wn == 1 && tig == 0) {
        #pragma unroll
        for (int i = 0; i < 4; i++) {
            int row = wm * 32 + (i >> 1) * 16 + g + (i & 1) * 8;
            part[row] = rowsum[i];
        }
    }
    __syncthreads();
    if (wn == 0 && tig == 0) {
        float bias2 = b2[0];
        #pragma unroll
        for (int i = 0; i < 4; i++) {
            int row = wm * 32 + (i >> 1) * 16 + g + (i & 1) * 8;
            float t = rowsum[i] + part[row] + bias2;
            int e = tile * M_TILE + row;
            if (e < E) out[e] = 1.f / (1.f + __expf(-t));
        }
    }
}

// ---------------- Launch ----------------
extern "C" void kernel_launch(void* const* d_in, const int* in_sizes, int n_in,
                              void* d_out, int out_size) {
    const int*   src = (const int*)d_in[0];
    const int*   dst = (const int*)d_in[1];
    const float* h   = (const float*)d_in[2];
    const float* W1  = (const float*)d_in[3];
    const float* b1  = (const float*)d_in[4];
    const float* W2  = (const float*)d_in[5];
    const float* b2  = (const float*)d_in[6];
    float* out = (float*)d_out;

    const int E   = in_sizes[0];
    const int n_h = in_sizes[2];

    int n4h = n_h / 4;
    conv_h_kernel<<<(n4h + 255) / 256, 256>>>(h, n4h);
    int n4w = (HIDDEN * KDIM) / 4;
    conv_w1_kernel<<<(n4w + 255) / 256, 256>>>(W1, n4w);

    cudaFuncSetAttribute(edge_mlp_kernel, cudaFuncAttributeMaxDynamicSharedMemorySize, SM_TOTAL);
    int n_tiles = (E + M_TILE - 1) / M_TILE;
    edge_mlp_kernel<<<n_tiles, 256, SM_TOTAL>>>(src, dst, b1, W2, b2, out, E);
}

// round 5
// speedup vs baseline: 1.5934x; 1.5934x over previous
#include <cuda_runtime.h>
#include <cuda_fp16.h>
#include <cstdint>

#define IN_FEATS   128
#define HIDDEN     128
#define KDIM       256           // 2 * IN_FEATS
#define M_TILE     128           // edges per tile
#define MAX_NODES  100000
#define NUM_KSTEP  16            // KDIM / 16

// Persistent scratch (allocation-free rule: __device__ globals)
__device__ __align__(16) __half g_h16[MAX_NODES * IN_FEATS];   // fp16 copy of h
__device__ __align__(16) __half g_w1h[HIDDEN * KDIM];          // fp16 W1, row-major [n][k]

// ---------------- SMEM layout ----------------
// Padded rows: 256 halfs + 8 pad = 264 halfs = 528 B stride.
#define A_STRIDE_H 264
#define TILE_BYTES (128 * A_STRIDE_H * 2)     // 67584
#define SM_B     0                            // W1 tile (resident whole kernel)
#define SM_A0    TILE_BYTES                   // A double buffer
#define SM_A1    (2 * TILE_BYTES)
#define SM_B1    (3 * TILE_BYTES)             // 128 f32 bias1
#define SM_W2    (SM_B1 + 512)                // 128 f32
#define SM_PART  (SM_W2 + 512)                // 128 f32 partials
#define SM_TOTAL (SM_PART + 512)              // 204288 B (~199.5 KB)

__device__ __forceinline__ uint32_t smem_u32(const void* p) {
    uint32_t a;
    asm("{ .reg .u64 t; cvta.to.shared.u64 t, %1; cvt.u32.u64 %0, t; }" : "=r"(a) : "l"(p));
    return a;
}

#define LDMATRIX_X4(r0, r1, r2, r3, addr) \
    asm volatile("ldmatrix.sync.aligned.m8n8.x4.shared.b16 {%0,%1,%2,%3}, [%4];" \
                 : "=r"(r0), "=r"(r1), "=r"(r2), "=r"(r3) : "r"(addr))

#define MMA16816(c0, c1, c2, c3, a0, a1, a2, a3, b0, b1) \
    asm volatile("mma.sync.aligned.m16n8k16.row.col.f32.f16.f16.f32 " \
                 "{%0,%1,%2,%3}, {%4,%5,%6,%7}, {%8,%9}, {%0,%1,%2,%3};" \
                 : "+f"(c0), "+f"(c1), "+f"(c2), "+f"(c3) \
                 : "r"(a0), "r"(a1), "r"(a2), "r"(a3), "r"(b0), "r"(b1))

#define CP_ASYNC_16(smem_addr, gptr) \
    asm volatile("cp.async.cg.shared.global [%0], [%1], 16;" \
                 :: "r"(smem_addr), "l"(gptr) : "memory")
#define CP_COMMIT()  asm volatile("cp.async.commit_group;" ::: "memory")
#define CP_WAIT_1()  asm volatile("cp.async.wait_group 1;" ::: "memory")

// ---------------- Prep kernels ----------------
__global__ void conv_h_kernel(const float* __restrict__ h, int n4) {
    int i = blockIdx.x * blockDim.x + threadIdx.x;
    if (i < n4) {
        float4 v = reinterpret_cast<const float4*>(h)[i];
        __half2* o2 = reinterpret_cast<__half2*>(g_h16);
        o2[i * 2 + 0] = __floats2half2_rn(v.x, v.y);
        o2[i * 2 + 1] = __floats2half2_rn(v.z, v.w);
    }
}

__global__ void conv_w1_kernel(const float* __restrict__ W1, int n4) {
    int i = blockIdx.x * blockDim.x + threadIdx.x;
    if (i < n4) {
        float4 v = reinterpret_cast<const float4*>(W1)[i];
        __half2* o2 = reinterpret_cast<__half2*>(g_w1h);
        o2[i * 2 + 0] = __floats2half2_rn(v.x, v.y);
        o2[i * 2 + 1] = __floats2half2_rn(v.z, v.w);
    }
}

// ---------------- Main fused persistent kernel ----------------
// Grid = #SMs. Each CTA: load W1 once, then loop tiles with cp.async
// double-buffered gather overlapped against HMMA compute.
__global__ void __launch_bounds__(256, 1)
edge_mlp_kernel(const int* __restrict__ src, const int* __restrict__ dst,
                const float* __restrict__ b1, const float* __restrict__ W2,
                const float* __restrict__ b2, float* __restrict__ out,
                int E, int n_tiles)
{
    extern __shared__ char smem[];
    const int tid = threadIdx.x;
    const int wid = tid >> 5;
    const int lid = tid & 31;
    const uint32_t sb = smem_u32(smem);

    // Stage bias/W2 once
    if (tid < 128) {
        reinterpret_cast<float*>(smem + SM_B1)[tid] = b1[tid];
        reinterpret_cast<float*>(smem + SM_W2)[tid] = W2[tid];
    }
    // Load W1 tile once (resident for whole kernel)
    {
        const int j  = tid & 31;
        const int rg = tid >> 5;
        #pragma unroll
        for (int g = 0; g < 16; g++) {
            int n = g * 8 + rg;
            const uint4* rowp = reinterpret_cast<const uint4*>(g_w1h + n * KDIM);
            *reinterpret_cast<uint4*>(smem + SM_B + n * (A_STRIDE_H * 2) + j * 16) = rowp[j];
        }
    }

    const int stride = gridDim.x;
    const int t0 = blockIdx.x;
    if (t0 >= n_tiles) return;

    // Gather issue: 16 chunks of 16B per thread into buffer `bufo`
    const int j  = tid & 31;            // 16B chunk within 512B logical row
    const int rg = tid >> 5;
    const int hf = j >> 4;              // 0 = src half, 1 = dst half
    const int jc = j & 15;
    const int* epick = hf ? dst : src;

    auto issue_gather = [&](int t, uint32_t abase) {
        #pragma unroll
        for (int g = 0; g < 16; g++) {
            int r = g * 8 + rg;
            int e = t * M_TILE + r;
            int idx = (e < E) ? epick[e] : 0;
            uint64_t gptr = __cvta_generic_to_global(g_h16 + (size_t)idx * IN_FEATS) + jc * 16;
            CP_ASYNC_16(abase + (uint32_t)(r * (A_STRIDE_H * 2) + j * 16), gptr);
        }
    };

    // Prologue: prefetch first tile into buf 0
    issue_gather(t0, sb + SM_A0);
    CP_COMMIT();

    const int wm = wid & 3;
    const int wn = wid >> 2;
    const int lr = lid & 15;
    const int lc = (lid >> 4) * 8;
    const int g8  = lid >> 2;
    const int tig = lid & 3;
    const float* b1s = reinterpret_cast<const float*>(smem + SM_B1);
    const float* w2s = reinterpret_cast<const float*>(smem + SM_W2);
    float* part = reinterpret_cast<float*>(smem + SM_PART);
    const float bias2 = b2[0];
    const uint32_t b_lane = sb + SM_B + (uint32_t)(wn * 64 + lr) * (A_STRIDE_H * 2) + (uint32_t)lc * 2;

    int buf = 0;
    for (int t = t0; t < n_tiles; t += stride) {
        // Prefetch next tile into the other buffer
        int tn = t + stride;
        if (tn < n_tiles) issue_gather(tn, sb + (buf ? SM_A0 : SM_A1));
        CP_COMMIT();
        CP_WAIT_1();              // current tile's gather complete
        __syncthreads();

        const uint32_t abase = sb + (buf ? SM_A1 : SM_A0);
        const uint32_t a_lane = abase + (uint32_t)(wm * 32 + lr) * (A_STRIDE_H * 2) + (uint32_t)lc * 2;

        float acc[2][8][4];
        #pragma unroll
        for (int mt = 0; mt < 2; mt++)
            #pragma unroll
            for (int nt = 0; nt < 8; nt++)
                #pragma unroll
                for (int c = 0; c < 4; c++) acc[mt][nt][c] = 0.f;

        #pragma unroll
        for (int ks = 0; ks < NUM_KSTEP; ks++) {
            const uint32_t koff = (uint32_t)(ks * 16) * 2;
            uint32_t a0[4], a1[4];
            LDMATRIX_X4(a0[0], a0[1], a0[2], a0[3], a_lane + koff);
            LDMATRIX_X4(a1[0], a1[1], a1[2], a1[3], a_lane + (uint32_t)(16 * A_STRIDE_H * 2) + koff);
            uint32_t bf[4][4];
            #pragma unroll
            for (int ntp = 0; ntp < 4; ntp++) {
                LDMATRIX_X4(bf[ntp][0], bf[ntp][1], bf[ntp][2], bf[ntp][3],
                            b_lane + (uint32_t)(ntp * 16 * A_STRIDE_H * 2) + koff);
            }
            #pragma unroll
            for (int ntp = 0; ntp < 4; ntp++) {
                MMA16816(acc[0][2*ntp][0], acc[0][2*ntp][1], acc[0][2*ntp][2], acc[0][2*ntp][3],
                         a0[0], a0[1], a0[2], a0[3], bf[ntp][0], bf[ntp][2]);
                MMA16816(acc[0][2*ntp+1][0], acc[0][2*ntp+1][1], acc[0][2*ntp+1][2], acc[0][2*ntp+1][3],
                         a0[0], a0[1], a0[2], a0[3], bf[ntp][1], bf[ntp][3]);
                MMA16816(acc[1][2*ntp][0], acc[1][2*ntp][1], acc[1][2*ntp][2], acc[1][2*ntp][3],
                         a1[0], a1[1], a1[2], a1[3], bf[ntp][0], bf[ntp][2]);
                MMA16816(acc[1][2*ntp+1][0], acc[1][2*ntp+1][1], acc[1][2*ntp+1][2], acc[1][2*ntp+1][3],
                         a1[0], a1[1], a1[2], a1[3], bf[ntp][1], bf[ntp][3]);
            }
        }

        // Fused epilogue: +b1, ReLU, dot W2, quad-reduce, combine halves, sigmoid
        float rowsum[4];
        #pragma unroll
        for (int mt = 0; mt < 2; mt++) {
            #pragma unroll
            for (int hh = 0; hh < 2; hh++) {
                float s = 0.f;
                #pragma unroll
                for (int nt = 0; nt < 8; nt++) {
                    int col = wn * 64 + nt * 8 + tig * 2;
                    float v0 = fmaxf(acc[mt][nt][hh * 2 + 0] + b1s[col], 0.f);
                    float v1 = fmaxf(acc[mt][nt][hh * 2 + 1] + b1s[col + 1], 0.f);
                    s = fmaf(v0, w2s[col], s);
                    s = fmaf(v1, w2s[col + 1], s);
                }
                rowsum[mt * 2 + hh] = s;
            }
        }
        #pragma unroll
        for (int i = 0; i < 4; i++) {
            rowsum[i] += __shfl_xor_sync(0xFFFFFFFF, rowsum[i], 1);
            rowsum[i] += __shfl_xor_sync(0xFFFFFFFF, rowsum[i], 2);
        }

        if (wn == 1 && tig == 0) {
            #pragma unroll
            for (int i = 0; i < 4; i++) {
                int row = wm * 32 + (i >> 1) * 16 + g8 + (i & 1) * 8;
                part[row] = rowsum[i];
            }
        }
        __syncthreads();
        if (wn == 0 && tig == 0) {
            #pragma unroll
            for (int i = 0; i < 4; i++) {
                int row = wm * 32 + (i >> 1) * 16 + g8 + (i & 1) * 8;
                float v = rowsum[i] + part[row] + bias2;
                int e = t * M_TILE + row;
                if (e < E) out[e] = 1.f / (1.f + __expf(-v));
            }
        }
        __syncthreads();   // all reads of buf + part done before next iter's cp.async/writes
        buf ^= 1;
    }
}

// ---------------- Launch ----------------
extern "C" void kernel_launch(void* const* d_in, const int* in_sizes, int n_in,
                              void* d_out, int out_size) {
    const int*   src = (const int*)d_in[0];
    const int*   dst = (const int*)d_in[1];
    const float* h   = (const float*)d_in[2];
    const float* W1  = (const float*)d_in[3];
    const float* b1  = (const float*)d_in[4];
    const float* W2  = (const float*)d_in[5];
    const float* b2  = (const float*)d_in[6];
    float* out = (float*)d_out;

    const int E   = in_sizes[0];
    const int n_h = in_sizes[2];

    int n4h = n_h / 4;
    conv_h_kernel<<<(n4h + 255) / 256, 256>>>(h, n4h);
    int n4w = (HIDDEN * KDIM) / 4;
    conv_w1_kernel<<<(n4w + 255) / 256, 256>>>(W1, n4w);

    int dev = 0, sms = 148;
    cudaGetDevice(&dev);
    cudaDeviceGetAttribute(&sms, cudaDevAttrMultiProcessorCount, dev);

    cudaFuncSetAttribute(edge_mlp_kernel, cudaFuncAttributeMaxDynamicSharedMemorySize, SM_TOTAL);
    int n_tiles = (E + M_TILE - 1) / M_TILE;
    int grid = (n_tiles < sms) ? n_tiles : sms;
    edge_mlp_kernel<<<grid, 256, SM_TOTAL>>>(src, dst, b1, W2, b2, out, E, n_tiles);
}

// round 6
// speedup vs baseline: 1.7348x; 1.0887x over previous
#include <cuda_runtime.h>
#include <cuda_fp16.h>
#include <cstdint>

#define IN_FEATS   128
#define HIDDEN     128
#define KDIM       256           // 2 * IN_FEATS
#define M_TILE     128           // edges per tile
#define MAX_NODES  100000
#define NUM_KSTEP  16            // KDIM / 16

// Persistent scratch (allocation-free rule: __device__ globals)
__device__ __align__(16) __half g_h16[MAX_NODES * IN_FEATS];   // fp16 copy of h
__device__ __align__(16) __half g_w1h[HIDDEN * KDIM];          // fp16 W1, row-major [n][k]

// ---------------- SMEM layout ----------------
// Padded rows: 256 halfs + 8 pad = 264 halfs = 528 B stride (conflict-free ldmatrix).
#define A_STRIDE_H 264
#define ROW_B      (A_STRIDE_H * 2)           // 528 bytes
#define TILE_BYTES (128 * ROW_B)              // 67584
#define SM_B     0                            // W1 tile (resident whole kernel)
#define SM_A0    TILE_BYTES                   // A double buffer
#define SM_A1    (2 * TILE_BYTES)
#define SM_B1    (3 * TILE_BYTES)             // 128 f32 bias1
#define SM_W2    (SM_B1 + 512)                // 128 f32
#define SM_PART  (SM_W2 + 512)                // 4 x 128 f32 partials
#define SM_TOTAL (SM_PART + 2048)             // 205824 B (~201 KB)

__device__ __forceinline__ uint32_t smem_u32(const void* p) {
    uint32_t a;
    asm("{ .reg .u64 t; cvta.to.shared.u64 t, %1; cvt.u32.u64 %0, t; }" : "=r"(a) : "l"(p));
    return a;
}

#define LDMATRIX_X4(r0, r1, r2, r3, addr) \
    asm volatile("ldmatrix.sync.aligned.m8n8.x4.shared.b16 {%0,%1,%2,%3}, [%4];" \
                 : "=r"(r0), "=r"(r1), "=r"(r2), "=r"(r3) : "r"(addr))

#define MMA16816(c0, c1, c2, c3, a0, a1, a2, a3, b0, b1) \
    asm volatile("mma.sync.aligned.m16n8k16.row.col.f32.f16.f16.f32 " \
                 "{%0,%1,%2,%3}, {%4,%5,%6,%7}, {%8,%9}, {%0,%1,%2,%3};" \
                 : "+f"(c0), "+f"(c1), "+f"(c2), "+f"(c3) \
                 : "r"(a0), "r"(a1), "r"(a2), "r"(a3), "r"(b0), "r"(b1))

#define CP_ASYNC_16(smem_addr, gptr) \
    asm volatile("cp.async.cg.shared.global [%0], [%1], 16;" \
                 :: "r"(smem_addr), "l"(gptr) : "memory")
#define CP_COMMIT()  asm volatile("cp.async.commit_group;" ::: "memory")
#define CP_WAIT_1()  asm volatile("cp.async.wait_group 1;" ::: "memory")

// ---------------- Prep kernels (2 float4 per thread for ILP) ----------------
__global__ void conv_h_kernel(const float* __restrict__ h, int n4) {
    int i = (blockIdx.x * blockDim.x + threadIdx.x) * 2;
    __half2* o2 = reinterpret_cast<__half2*>(g_h16);
    if (i + 1 < n4) {
        float4 v0 = reinterpret_cast<const float4*>(h)[i];
        float4 v1 = reinterpret_cast<const float4*>(h)[i + 1];
        o2[i * 2 + 0] = __floats2half2_rn(v0.x, v0.y);
        o2[i * 2 + 1] = __floats2half2_rn(v0.z, v0.w);
        o2[i * 2 + 2] = __floats2half2_rn(v1.x, v1.y);
        o2[i * 2 + 3] = __floats2half2_rn(v1.z, v1.w);
    } else if (i < n4) {
        float4 v0 = reinterpret_cast<const float4*>(h)[i];
        o2[i * 2 + 0] = __floats2half2_rn(v0.x, v0.y);
        o2[i * 2 + 1] = __floats2half2_rn(v0.z, v0.w);
    }
}

__global__ void conv_w1_kernel(const float* __restrict__ W1, int n4) {
    int i = blockIdx.x * blockDim.x + threadIdx.x;
    if (i < n4) {
        float4 v = reinterpret_cast<const float4*>(W1)[i];
        __half2* o2 = reinterpret_cast<__half2*>(g_w1h);
        o2[i * 2 + 0] = __floats2half2_rn(v.x, v.y);
        o2[i * 2 + 1] = __floats2half2_rn(v.z, v.w);
    }
}

// ---------------- Main fused persistent kernel ----------------
// Grid = #SMs. Warp grid 2(M) x 4(N): warp = 64 rows x 32 cols.
// W1 fragments preloaded into 128 registers per thread, reused across tiles.
__global__ void __launch_bounds__(256, 1)
edge_mlp_kernel(const int* __restrict__ src, const int* __restrict__ dst,
                const float* __restrict__ b1, const float* __restrict__ W2,
                const float* __restrict__ b2, float* __restrict__ out,
                int E, int n_tiles)
{
    extern __shared__ char smem[];
    const int tid = threadIdx.x;
    const int wid = tid >> 5;
    const int lid = tid & 31;
    const uint32_t sb = smem_u32(smem);

    // Stage bias/W2 once
    if (tid < 128) {
        reinterpret_cast<float*>(smem + SM_B1)[tid] = b1[tid];
        reinterpret_cast<float*>(smem + SM_W2)[tid] = W2[tid];
    }
    // Load W1 tile into SMEM once
    {
        const int j  = tid & 31;
        const int rg = tid >> 5;
        #pragma unroll
        for (int g = 0; g < 16; g++) {
            int n = g * 8 + rg;
            const uint4* rowp = reinterpret_cast<const uint4*>(g_w1h + n * KDIM);
            *reinterpret_cast<uint4*>(smem + SM_B + n * ROW_B + j * 16) = rowp[j];
        }
    }
    __syncthreads();

    const int wm = wid >> 2;              // 0..1: rows wm*64..+63
    const int wn = wid & 3;               // 0..3: cols wn*32..+31
    const int lr = lid & 15;
    const int lc = (lid >> 4) * 8;

    // ---- Preload B (W1) fragments into registers: 16 ksteps x 8 regs ----
    uint32_t breg[NUM_KSTEP][8];
    {
        const uint32_t b_lane = sb + SM_B + (uint32_t)(wn * 32 + lr) * ROW_B + (uint32_t)lc * 2;
        #pragma unroll
        for (int ks = 0; ks < NUM_KSTEP; ks++) {
            const uint32_t koff = (uint32_t)ks * 32;
            LDMATRIX_X4(breg[ks][0], breg[ks][1], breg[ks][2], breg[ks][3], b_lane + koff);
            LDMATRIX_X4(breg[ks][4], breg[ks][5], breg[ks][6], breg[ks][7],
                        b_lane + (uint32_t)(16 * ROW_B) + koff);
        }
    }

    const int stride = gridDim.x;
    const int t0 = blockIdx.x;
    if (t0 >= n_tiles) return;

    // Gather: 16 chunks of 16B per thread per tile
    const int j  = tid & 31;
    const int rg = tid >> 5;
    const int hf = j >> 4;
    const int jc = j & 15;
    const int* epick = hf ? dst : src;

    auto issue_gather = [&](int t, uint32_t abase) {
        #pragma unroll
        for (int g = 0; g < 16; g++) {
            int r = g * 8 + rg;
            int e = t * M_TILE + r;
            int idx = (e < E) ? epick[e] : 0;
            uint64_t gptr = __cvta_generic_to_global(g_h16 + (size_t)idx * IN_FEATS) + jc * 16;
            CP_ASYNC_16(abase + (uint32_t)(r * ROW_B + j * 16), gptr);
        }
    };

    issue_gather(t0, sb + SM_A0);
    CP_COMMIT();

    const int g8  = lid >> 2;
    const int tig = lid & 3;
    const float* b1s = reinterpret_cast<const float*>(smem + SM_B1);
    const float* w2s = reinterpret_cast<const float*>(smem + SM_W2);
    float* part = reinterpret_cast<float*>(smem + SM_PART);
    const float bias2 = b2[0];

    int buf = 0;
    for (int t = t0; t < n_tiles; t += stride) {
        int tn = t + stride;
        if (tn < n_tiles) issue_gather(tn, sb + (buf ? SM_A0 : SM_A1));
        CP_COMMIT();
        CP_WAIT_1();
        __syncthreads();

        const uint32_t abase = sb + (buf ? SM_A1 : SM_A0);
        const uint32_t a_lane = abase + (uint32_t)(wm * 64 + lr) * ROW_B + (uint32_t)lc * 2;

        float acc[4][4][4];
        #pragma unroll
        for (int mt = 0; mt < 4; mt++)
            #pragma unroll
            for (int nt = 0; nt < 4; nt++)
                #pragma unroll
                for (int c = 0; c < 4; c++) acc[mt][nt][c] = 0.f;

        #pragma unroll
        for (int ks = 0; ks < NUM_KSTEP; ks++) {
            const uint32_t koff = (uint32_t)ks * 32;
            uint32_t a[4][4];
            #pragma unroll
            for (int mt = 0; mt < 4; mt++) {
                LDMATRIX_X4(a[mt][0], a[mt][1], a[mt][2], a[mt][3],
                            a_lane + (uint32_t)(mt * 16 * ROW_B) + koff);
            }
            #pragma unroll
            for (int mt = 0; mt < 4; mt++) {
                #pragma unroll
                for (int np = 0; np < 2; np++) {
                    MMA16816(acc[mt][2*np][0], acc[mt][2*np][1], acc[mt][2*np][2], acc[mt][2*np][3],
                             a[mt][0], a[mt][1], a[mt][2], a[mt][3],
                             breg[ks][np*4 + 0], breg[ks][np*4 + 2]);
                    MMA16816(acc[mt][2*np+1][0], acc[mt][2*np+1][1], acc[mt][2*np+1][2], acc[mt][2*np+1][3],
                             a[mt][0], a[mt][1], a[mt][2], a[mt][3],
                             breg[ks][np*4 + 1], breg[ks][np*4 + 3]);
                }
            }
        }

        // ---- Fused epilogue ----
        float rowsum[8];                   // [mt*2 + hh]
        #pragma unroll
        for (int mt = 0; mt < 4; mt++) {
            #pragma unroll
            for (int hh = 0; hh < 2; hh++) {
                float s = 0.f;
                #pragma unroll
                for (int nt = 0; nt < 4; nt++) {
                    int col = wn * 32 + nt * 8 + tig * 2;
                    float v0 = fmaxf(acc[mt][nt][hh * 2 + 0] + b1s[col], 0.f);
                    float v1 = fmaxf(acc[mt][nt][hh * 2 + 1] + b1s[col + 1], 0.f);
                    s = fmaf(v0, w2s[col], s);
                    s = fmaf(v1, w2s[col + 1], s);
                }
                rowsum[mt * 2 + hh] = s;
            }
        }
        #pragma unroll
        for (int i = 0; i < 8; i++) {
            rowsum[i] += __shfl_xor_sync(0xFFFFFFFF, rowsum[i], 1);
            rowsum[i] += __shfl_xor_sync(0xFFFFFFFF, rowsum[i], 2);
        }
        if (tig == 0) {
            #pragma unroll
            for (int i = 0; i < 8; i++) {
                int row = wm * 64 + (i >> 1) * 16 + g8 + (i & 1) * 8;
                part[wn * 128 + row] = rowsum[i];
            }
        }
        __syncthreads();
        if (tid < 128) {
            float v = part[tid] + part[128 + tid] + part[256 + tid] + part[384 + tid] + bias2;
            int e = t * M_TILE + tid;
            if (e < E) out[e] = 1.f / (1.f + __expf(-v));
        }
        __syncthreads();
        buf ^= 1;
    }
}

// ---------------- Launch ----------------
extern "C" void kernel_launch(void* const* d_in, const int* in_sizes, int n_in,
                              void* d_out, int out_size) {
    const int*   src = (const int*)d_in[0];
    const int*   dst = (const int*)d_in[1];
    const float* h   = (const float*)d_in[2];
    const float* W1  = (const float*)d_in[3];
    const float* b1  = (const float*)d_in[4];
    const float* W2  = (const float*)d_in[5];
    const float* b2  = (const float*)d_in[6];
    float* out = (float*)d_out;

    const int E   = in_sizes[0];
    const int n_h = in_sizes[2];

    int n4h = n_h / 4;
    int nth = (n4h + 1) / 2;
    conv_h_kernel<<<(nth + 255) / 256, 256>>>(h, n4h);
    int n4w = (HIDDEN * KDIM) / 4;
    conv_w1_kernel<<<(n4w + 255) / 256, 256>>>(W1, n4w);

    int dev = 0, sms = 148;
    cudaGetDevice(&dev);
    cudaDeviceGetAttribute(&sms, cudaDevAttrMultiProcessorCount, dev);

    cudaFuncSetAttribute(edge_mlp_kernel, cudaFuncAttributeMaxDynamicSharedMemorySize, SM_TOTAL);
    int n_tiles = (E + M_TILE - 1) / M_TILE;
    int grid = (n_tiles < sms) ? n_tiles : sms;
    edge_mlp_kernel<<<grid, 256, SM_TOTAL>>>(src, dst, b1, W2, b2, out, E, n_tiles);
}

// round 7
// speedup vs baseline: 2.6471x; 1.5259x over previous
#include <cuda_runtime.h>
#include <cuda_fp16.h>
#include <cstdint>

#define IN_FEATS   128
#define HIDDEN     128
#define MAX_NODES  100000
#define NTILE      64            // node rows per GEMM tile
#define BSTR_H     136           // SMEM row stride in halfs (272 B, conflict-free ldmatrix)

// P|Q per node: 256 halfs = 512 B.  [P(128) | Q(128)]
__device__ __align__(16) __half g_pq[MAX_NODES * 256];

__device__ __forceinline__ uint32_t smem_u32(const void* p) {
    uint32_t a;
    asm("{ .reg .u64 t; cvta.to.shared.u64 t, %1; cvt.u32.u64 %0, t; }" : "=r"(a) : "l"(p));
    return a;
}

#define LDMATRIX_X4(r0, r1, r2, r3, addr) \
    asm volatile("ldmatrix.sync.aligned.m8n8.x4.shared.b16 {%0,%1,%2,%3}, [%4];" \
                 : "=r"(r0), "=r"(r1), "=r"(r2), "=r"(r3) : "r"(addr))

#define MMA16816(c0, c1, c2, c3, a0, a1, a2, a3, b0, b1) \
    asm volatile("mma.sync.aligned.m16n8k16.row.col.f32.f16.f16.f32 " \
                 "{%0,%1,%2,%3}, {%4,%5,%6,%7}, {%8,%9}, {%0,%1,%2,%3};" \
                 : "+f"(c0), "+f"(c1), "+f"(c2), "+f"(c3) \
                 : "r"(a0), "r"(a1), "r"(a2), "r"(a3), "r"(b0), "r"(b1))

// ---------------- SMEM layout for GEMM ----------------
#define SM_B      0                               // 256 rows x 136 halfs = 69632 B
#define SM_A      (256 * BSTR_H * 2)              // 64 rows x 136 halfs = 17408 B
#define SM_TOTAL  (SM_A + NTILE * BSTR_H * 2)     // 87040 B

// =====================================================================
// Phase 1: PQ[100K, 256] = h[100K,128] @ B[128k, 256n]
//   B row n' (output col): n'<128 -> W1[n'][k]  (P);  n'>=128 -> W1[n'-128][128+k] (Q)
// Persistent CTAs; W1 converted fp32->fp16 into SMEM once per CTA;
// A tile prefetched into registers (fp32), converted to SMEM fp16 per tile.
// =====================================================================
__global__ void __launch_bounds__(256, 1)
pq_gemm_kernel(const float* __restrict__ h, const float* __restrict__ W1,
               int n_nodes, int n_tiles)
{
    extern __shared__ char smem[];
    const int tid = threadIdx.x;
    const int wid = tid >> 5;
    const int lid = tid & 31;
    const uint32_t sb = smem_u32(smem);

    // ---- Load + convert B (W1) into SMEM once: 256 rows x 128 halfs ----
    {
        #pragma unroll
        for (int i = 0; i < 32; i++) {
            int idx = tid + i * 256;              // 8192 float4 total
            int n2 = idx >> 5;                    // output col row 0..255
            int k  = (idx & 31) * 4;
            int wrow = n2 & 127;
            int kof  = (n2 >> 7) * 128;
            float4 v = *reinterpret_cast<const float4*>(W1 + wrow * 256 + kof + k);
            __half2* dp = reinterpret_cast<__half2*>(smem + SM_B + (n2 * BSTR_H + k) * 2);
            dp[0] = __floats2half2_rn(v.x, v.y);
            dp[1] = __floats2half2_rn(v.z, v.w);
        }
    }

    int t = blockIdx.x;
    if (t >= n_tiles) return;

    // A-register prefetch: 8 float4 per thread = one 64x128 f32 tile
    float4 areg[8];
    auto load_a = [&](int tt) {
        #pragma unroll
        for (int i = 0; i < 8; i++) {
            int idx = tid + i * 256;
            int row = idx >> 5;
            int k   = (idx & 31) * 4;
            int grow = tt * NTILE + row;
            if (grow >= n_nodes) grow = 0;        // clamp (values unused)
            areg[i] = *reinterpret_cast<const float4*>(h + (size_t)grow * IN_FEATS + k);
        }
    };
    load_a(t);

    const int wm = wid >> 2;                      // 0..1 : rows wm*32
    const int wn = wid & 3;                       // 0..3 : cols wn*64
    const int lr = lid & 15;
    const int lc = (lid >> 4) * 8;
    const int g8  = lid >> 2;
    const int tig = lid & 3;

    const uint32_t b_lane = sb + SM_B + (uint32_t)(wn * 64 + lr) * (BSTR_H * 2) + (uint32_t)lc * 2;
    const uint32_t a_lane = sb + SM_A + (uint32_t)(wm * 32 + lr) * (BSTR_H * 2) + (uint32_t)lc * 2;

    for (; t < n_tiles; t += gridDim.x) {
        // convert prefetched A regs into SMEM fp16
        #pragma unroll
        for (int i = 0; i < 8; i++) {
            int idx = tid + i * 256;
            int row = idx >> 5;
            int k   = (idx & 31) * 4;
            __half2* dp = reinterpret_cast<__half2*>(smem + SM_A + (row * BSTR_H + k) * 2);
            dp[0] = __floats2half2_rn(areg[i].x, areg[i].y);
            dp[1] = __floats2half2_rn(areg[i].z, areg[i].w);
        }
        __syncthreads();

        int tn = t + gridDim.x;
        if (tn < n_tiles) load_a(tn);             // hidden under MMA

        float acc[2][8][4];
        #pragma unroll
        for (int mt = 0; mt < 2; mt++)
            #pragma unroll
            for (int nt = 0; nt < 8; nt++)
                #pragma unroll
                for (int c = 0; c < 4; c++) acc[mt][nt][c] = 0.f;

        #pragma unroll
        for (int ks = 0; ks < 8; ks++) {
            const uint32_t koff = (uint32_t)ks * 32;
            uint32_t a[2][4];
            #pragma unroll
            for (int mt = 0; mt < 2; mt++)
                LDMATRIX_X4(a[mt][0], a[mt][1], a[mt][2], a[mt][3],
                            a_lane + (uint32_t)(mt * 16 * BSTR_H * 2) + koff);
            uint32_t bf[4][4];
            #pragma unroll
            for (int ntp = 0; ntp < 4; ntp++)
                LDMATRIX_X4(bf[ntp][0], bf[ntp][1], bf[ntp][2], bf[ntp][3],
                            b_lane + (uint32_t)(ntp * 16 * BSTR_H * 2) + koff);
            #pragma unroll
            for (int mt = 0; mt < 2; mt++) {
                #pragma unroll
                for (int ntp = 0; ntp < 4; ntp++) {
                    MMA16816(acc[mt][2*ntp][0], acc[mt][2*ntp][1], acc[mt][2*ntp][2], acc[mt][2*ntp][3],
                             a[mt][0], a[mt][1], a[mt][2], a[mt][3], bf[ntp][0], bf[ntp][2]);
                    MMA16816(acc[mt][2*ntp+1][0], acc[mt][2*ntp+1][1], acc[mt][2*ntp+1][2], acc[mt][2*ntp+1][3],
                             a[mt][0], a[mt][1], a[mt][2], a[mt][3], bf[ntp][1], bf[ntp][3]);
                }
            }
        }

        // epilogue: fp16 store to g_pq
        #pragma unroll
        for (int mt = 0; mt < 2; mt++) {
            #pragma unroll
            for (int hh = 0; hh < 2; hh++) {
                int grow = t * NTILE + wm * 32 + mt * 16 + g8 + hh * 8;
                if (grow < n_nodes) {
                    #pragma unroll
                    for (int nt = 0; nt < 8; nt++) {
                        int col = wn * 64 + nt * 8 + tig * 2;
                        __half2 hv = __floats2half2_rn(acc[mt][nt][hh * 2 + 0],
                                                       acc[mt][nt][hh * 2 + 1]);
                        *reinterpret_cast<__half2*>(g_pq + (size_t)grow * 256 + col) = hv;
                    }
                }
            }
        }
        __syncthreads();   // all LDSM reads of A done before next tile's STS
    }
}

// =====================================================================
// Phase 2: per-edge score. Warp per edge: lane l owns hidden dims 4l..4l+3.
//   hidden = relu(P[src] + Q[dst] + b1); score = sigmoid(hidden . w2 + b2)
// =====================================================================
__global__ void __launch_bounds__(256)
edge_score_kernel(const int* __restrict__ src, const int* __restrict__ dst,
                  const float* __restrict__ b1, const float* __restrict__ W2,
                  const float* __restrict__ b2, float* __restrict__ out, int E)
{
    const int lane = threadIdx.x & 31;
    const int warp_gid = (blockIdx.x * blockDim.x + threadIdx.x) >> 5;
    const int nwarps = (gridDim.x * blockDim.x) >> 5;

    const float4 b1v = *reinterpret_cast<const float4*>(b1 + lane * 4);
    const float4 w2v = *reinterpret_cast<const float4*>(W2 + lane * 4);
    const float bias2 = b2[0];

    for (int e = warp_gid; e < E; e += nwarps) {
        int s = __ldg(src + e);
        int d = __ldg(dst + e);
        uint2 pu = *reinterpret_cast<const uint2*>(g_pq + (size_t)s * 256 + lane * 4);
        uint2 qu = *reinterpret_cast<const uint2*>(g_pq + (size_t)d * 256 + 128 + lane * 4);
        float2 p0 = __half22float2(*reinterpret_cast<__half2*>(&pu.x));
        float2 p1 = __half22float2(*reinterpret_cast<__half2*>(&pu.y));
        float2 q0 = __half22float2(*reinterpret_cast<__half2*>(&qu.x));
        float2 q1 = __half22float2(*reinterpret_cast<__half2*>(&qu.y));

        float v0 = fmaxf(p0.x + q0.x + b1v.x, 0.f);
        float v1 = fmaxf(p0.y + q0.y + b1v.y, 0.f);
        float v2 = fmaxf(p1.x + q1.x + b1v.z, 0.f);
        float v3 = fmaxf(p1.y + q1.y + b1v.w, 0.f);

        float acc = v0 * w2v.x;
        acc = fmaf(v1, w2v.y, acc);
        acc = fmaf(v2, w2v.z, acc);
        acc = fmaf(v3, w2v.w, acc);

        acc += __shfl_xor_sync(0xFFFFFFFF, acc, 16);
        acc += __shfl_xor_sync(0xFFFFFFFF, acc, 8);
        acc += __shfl_xor_sync(0xFFFFFFFF, acc, 4);
        acc += __shfl_xor_sync(0xFFFFFFFF, acc, 2);
        acc += __shfl_xor_sync(0xFFFFFFFF, acc, 1);

        if (lane == 0)
            out[e] = 1.f / (1.f + __expf(-(acc + bias2)));
    }
}

// ---------------- Launch ----------------
extern "C" void kernel_launch(void* const* d_in, const int* in_sizes, int n_in,
                              void* d_out, int out_size) {
    const int*   src = (const int*)d_in[0];
    const int*   dst = (const int*)d_in[1];
    const float* h   = (const float*)d_in[2];
    const float* W1  = (const float*)d_in[3];
    const float* b1  = (const float*)d_in[4];
    const float* W2  = (const float*)d_in[5];
    const float* b2  = (const float*)d_in[6];
    float* out = (float*)d_out;

    const int E       = in_sizes[0];
    const int n_nodes = in_sizes[2] / IN_FEATS;

    int dev = 0, sms = 148;
    cudaGetDevice(&dev);
    cudaDeviceGetAttribute(&sms, cudaDevAttrMultiProcessorCount, dev);

    // Phase 1: node-level GEMM (persistent)
    cudaFuncSetAttribute(pq_gemm_kernel, cudaFuncAttributeMaxDynamicSharedMemorySize, SM_TOTAL);
    int n_tiles = (n_nodes + NTILE - 1) / NTILE;
    int grid1 = (n_tiles < sms) ? n_tiles : sms;
    pq_gemm_kernel<<<grid1, 256, SM_TOTAL>>>(h, W1, n_nodes, n_tiles);

    // Phase 2: edge scoring (8 blocks per SM for full occupancy)
    int grid2 = sms * 8;
    edge_score_kernel<<<grid2, 256>>>(src, dst, b1, W2, b2, out, E);
}

// round 8
// speedup vs baseline: 3.5384x; 1.3367x over previous
#include <cuda_runtime.h>
#include <cuda_fp16.h>
#include <cstdint>

#define IN_FEATS   128
#define HIDDEN     128
#define MAX_NODES  100000
#define NTILE      64            // node rows per GEMM tile
#define BSTR_H     136           // SMEM row stride in halfs (272 B, conflict-free ldmatrix)

// P'|Q per node: 256 halfs = 512 B.  [P+b1 (128) | Q (128)]
__device__ __align__(16) __half g_pq[MAX_NODES * 256];

__device__ __forceinline__ uint32_t smem_u32(const void* p) {
    uint32_t a;
    asm("{ .reg .u64 t; cvta.to.shared.u64 t, %1; cvt.u32.u64 %0, t; }" : "=r"(a) : "l"(p));
    return a;
}

#define LDMATRIX_X4(r0, r1, r2, r3, addr) \
    asm volatile("ldmatrix.sync.aligned.m8n8.x4.shared.b16 {%0,%1,%2,%3}, [%4];" \
                 : "=r"(r0), "=r"(r1), "=r"(r2), "=r"(r3) : "r"(addr))

#define MMA16816(c0, c1, c2, c3, a0, a1, a2, a3, b0, b1) \
    asm volatile("mma.sync.aligned.m16n8k16.row.col.f32.f16.f16.f32 " \
                 "{%0,%1,%2,%3}, {%4,%5,%6,%7}, {%8,%9}, {%0,%1,%2,%3};" \
                 : "+f"(c0), "+f"(c1), "+f"(c2), "+f"(c3) \
                 : "r"(a0), "r"(a1), "r"(a2), "r"(a3), "r"(b0), "r"(b1))

// ---------------- SMEM layout for GEMM ----------------
#define SM_B      0                               // 256 rows x 136 halfs = 69632 B
#define SM_A      (256 * BSTR_H * 2)              // 64 rows x 136 halfs = 17408 B
#define SM_B1S    (SM_A + NTILE * BSTR_H * 2)     // 128 f32 bias1
#define SM_TOTAL  (SM_B1S + 512)                  // 87552 B

// =====================================================================
// Phase 1: PQ[100K, 256] = h[100K,128] @ B[128k, 256n]  (+ b1 on P cols)
//   B row n' (output col): n'<128 -> W1[n'][k]  (P);  n'>=128 -> W1[n'-128][128+k] (Q)
// =====================================================================
__global__ void __launch_bounds__(256, 1)
pq_gemm_kernel(const float* __restrict__ h, const float* __restrict__ W1,
               const float* __restrict__ b1, int n_nodes, int n_tiles)
{
    extern __shared__ char smem[];
    const int tid = threadIdx.x;
    const int wid = tid >> 5;
    const int lid = tid & 31;
    const uint32_t sb = smem_u32(smem);

    if (tid < 128) reinterpret_cast<float*>(smem + SM_B1S)[tid] = b1[tid];

    // ---- Load + convert B (W1) into SMEM once: 256 rows x 128 halfs ----
    {
        #pragma unroll
        for (int i = 0; i < 32; i++) {
            int idx = tid + i * 256;              // 8192 float4 total
            int n2 = idx >> 5;                    // output col row 0..255
            int k  = (idx & 31) * 4;
            int wrow = n2 & 127;
            int kof  = (n2 >> 7) * 128;
            float4 v = *reinterpret_cast<const float4*>(W1 + wrow * 256 + kof + k);
            __half2* dp = reinterpret_cast<__half2*>(smem + SM_B + (n2 * BSTR_H + k) * 2);
            dp[0] = __floats2half2_rn(v.x, v.y);
            dp[1] = __floats2half2_rn(v.z, v.w);
        }
    }

    int t = blockIdx.x;
    if (t >= n_tiles) return;

    // A-register prefetch: 8 float4 per thread = one 64x128 f32 tile
    float4 areg[8];
    auto load_a = [&](int tt) {
        #pragma unroll
        for (int i = 0; i < 8; i++) {
            int idx = tid + i * 256;
            int row = idx >> 5;
            int k   = (idx & 31) * 4;
            int grow = tt * NTILE + row;
            if (grow >= n_nodes) grow = 0;        // clamp (values unused)
            areg[i] = *reinterpret_cast<const float4*>(h + (size_t)grow * IN_FEATS + k);
        }
    };
    load_a(t);

    const int wm = wid >> 2;                      // 0..1 : rows wm*32
    const int wn = wid & 3;                       // 0..3 : cols wn*64
    const int lr = lid & 15;
    const int lc = (lid >> 4) * 8;
    const int g8  = lid >> 2;
    const int tig = lid & 3;

    const uint32_t b_lane = sb + SM_B + (uint32_t)(wn * 64 + lr) * (BSTR_H * 2) + (uint32_t)lc * 2;
    const uint32_t a_lane = sb + SM_A + (uint32_t)(wm * 32 + lr) * (BSTR_H * 2) + (uint32_t)lc * 2;
    const float* b1s = reinterpret_cast<const float*>(smem + SM_B1S);
    const bool is_p = (wn < 2);                   // cols < 128 => P region

    for (; t < n_tiles; t += gridDim.x) {
        // convert prefetched A regs into SMEM fp16
        #pragma unroll
        for (int i = 0; i < 8; i++) {
            int idx = tid + i * 256;
            int row = idx >> 5;
            int k   = (idx & 31) * 4;
            __half2* dp = reinterpret_cast<__half2*>(smem + SM_A + (row * BSTR_H + k) * 2);
            dp[0] = __floats2half2_rn(areg[i].x, areg[i].y);
            dp[1] = __floats2half2_rn(areg[i].z, areg[i].w);
        }
        __syncthreads();

        int tn = t + gridDim.x;
        if (tn < n_tiles) load_a(tn);             // hidden under MMA

        float acc[2][8][4];
        #pragma unroll
        for (int mt = 0; mt < 2; mt++)
            #pragma unroll
            for (int nt = 0; nt < 8; nt++)
                #pragma unroll
                for (int c = 0; c < 4; c++) acc[mt][nt][c] = 0.f;

        #pragma unroll
        for (int ks = 0; ks < 8; ks++) {
            const uint32_t koff = (uint32_t)ks * 32;
            uint32_t a[2][4];
            #pragma unroll
            for (int mt = 0; mt < 2; mt++)
                LDMATRIX_X4(a[mt][0], a[mt][1], a[mt][2], a[mt][3],
                            a_lane + (uint32_t)(mt * 16 * BSTR_H * 2) + koff);
            uint32_t bf[4][4];
            #pragma unroll
            for (int ntp = 0; ntp < 4; ntp++)
                LDMATRIX_X4(bf[ntp][0], bf[ntp][1], bf[ntp][2], bf[ntp][3],
                            b_lane + (uint32_t)(ntp * 16 * BSTR_H * 2) + koff);
            #pragma unroll
            for (int mt = 0; mt < 2; mt++) {
                #pragma unroll
                for (int ntp = 0; ntp < 4; ntp++) {
                    MMA16816(acc[mt][2*ntp][0], acc[mt][2*ntp][1], acc[mt][2*ntp][2], acc[mt][2*ntp][3],
                             a[mt][0], a[mt][1], a[mt][2], a[mt][3], bf[ntp][0], bf[ntp][2]);
                    MMA16816(acc[mt][2*ntp+1][0], acc[mt][2*ntp+1][1], acc[mt][2*ntp+1][2], acc[mt][2*ntp+1][3],
                             a[mt][0], a[mt][1], a[mt][2], a[mt][3], bf[ntp][1], bf[ntp][3]);
                }
            }
        }

        // epilogue: (+b1 on P cols), fp16 store to g_pq
        #pragma unroll
        for (int mt = 0; mt < 2; mt++) {
            #pragma unroll
            for (int hh = 0; hh < 2; hh++) {
                int grow = t * NTILE + wm * 32 + mt * 16 + g8 + hh * 8;
                if (grow < n_nodes) {
                    #pragma unroll
                    for (int nt = 0; nt < 8; nt++) {
                        int col = wn * 64 + nt * 8 + tig * 2;
                        float v0 = acc[mt][nt][hh * 2 + 0];
                        float v1 = acc[mt][nt][hh * 2 + 1];
                        if (is_p) { v0 += b1s[col]; v1 += b1s[col + 1]; }
                        __half2 hv = __floats2half2_rn(v0, v1);
                        *reinterpret_cast<__half2*>(g_pq + (size_t)grow * 256 + col) = hv;
                    }
                }
            }
        }
        __syncthreads();   // all LDSM reads of A done before next tile's STS
    }
}

// =====================================================================
// Phase 2: per-edge score. 8 lanes per edge (4 edges per warp).
//   Lane oct owns dims [oct*8..+7] and [64+oct*8..+7] of the 128-dim hidden.
//   hidden = relu(P'[src] + Q[dst]); score = sigmoid(hidden . w2 + b2)
// =====================================================================
__device__ __forceinline__ float dot8(uint4 p, uint4 q, float4 w0, float4 w1) {
    const __half2 z = __float2half2_rn(0.f);
    __half2 h0 = __hmax2(__hadd2(*reinterpret_cast<__half2*>(&p.x),
                                 *reinterpret_cast<__half2*>(&q.x)), z);
    __half2 h1 = __hmax2(__hadd2(*reinterpret_cast<__half2*>(&p.y),
                                 *reinterpret_cast<__half2*>(&q.y)), z);
    __half2 h2 = __hmax2(__hadd2(*reinterpret_cast<__half2*>(&p.z),
                                 *reinterpret_cast<__half2*>(&q.z)), z);
    __half2 h3 = __hmax2(__hadd2(*reinterpret_cast<__half2*>(&p.w),
                                 *reinterpret_cast<__half2*>(&q.w)), z);
    float2 f0 = __half22float2(h0);
    float2 f1 = __half22float2(h1);
    float2 f2 = __half22float2(h2);
    float2 f3 = __half22float2(h3);
    float a = f0.x * w0.x;
    a = fmaf(f0.y, w0.y, a);
    a = fmaf(f1.x, w0.z, a);
    a = fmaf(f1.y, w0.w, a);
    a = fmaf(f2.x, w1.x, a);
    a = fmaf(f2.y, w1.y, a);
    a = fmaf(f3.x, w1.z, a);
    a = fmaf(f3.y, w1.w, a);
    return a;
}

__global__ void __launch_bounds__(256)
edge_score_kernel(const int* __restrict__ src, const int* __restrict__ dst,
                  const float* __restrict__ W2, const float* __restrict__ b2,
                  float* __restrict__ out, int E)
{
    const int lane = threadIdx.x & 31;
    const int oct  = lane & 7;           // dim octet within edge
    const int sub  = lane >> 3;          // edge within warp quad
    const int warp_gid = (blockIdx.x * blockDim.x + threadIdx.x) >> 5;
    const int nwarps = (gridDim.x * blockDim.x) >> 5;

    // W2 registers: dims oct*8..+7 and 64+oct*8..+7
    const float4 w2a0 = *reinterpret_cast<const float4*>(W2 + oct * 8);
    const float4 w2a1 = *reinterpret_cast<const float4*>(W2 + oct * 8 + 4);
    const float4 w2b0 = *reinterpret_cast<const float4*>(W2 + 64 + oct * 8);
    const float4 w2b1 = *reinterpret_cast<const float4*>(W2 + 64 + oct * 8 + 4);
    const float bias2 = b2[0];

    for (int base = warp_gid * 4; base < E; base += nwarps * 4) {
        int e = base + sub;
        bool valid = e < E;
        int ei = valid ? e : (E - 1);
        int s = __ldg(src + ei);
        int d = __ldg(dst + ei);

        const char* prow = reinterpret_cast<const char*>(g_pq) + (size_t)s * 512;
        const char* qrow = reinterpret_cast<const char*>(g_pq) + (size_t)d * 512 + 256;
        // dims oct*8..+7 (bytes oct*16), dims 64+oct*8..+7 (bytes 128+oct*16)
        uint4 pa = *reinterpret_cast<const uint4*>(prow + oct * 16);
        uint4 pb = *reinterpret_cast<const uint4*>(prow + 128 + oct * 16);
        uint4 qa = *reinterpret_cast<const uint4*>(qrow + oct * 16);
        uint4 qb = *reinterpret_cast<const uint4*>(qrow + 128 + oct * 16);

        float acc = dot8(pa, qa, w2a0, w2a1) + dot8(pb, qb, w2b0, w2b1);
        acc += __shfl_xor_sync(0xFFFFFFFF, acc, 1);
        acc += __shfl_xor_sync(0xFFFFFFFF, acc, 2);
        acc += __shfl_xor_sync(0xFFFFFFFF, acc, 4);

        if (oct == 0 && valid)
            out[e] = 1.f / (1.f + __expf(-(acc + bias2)));
    }
}

// ---------------- Launch ----------------
extern "C" void kernel_launch(void* const* d_in, const int* in_sizes, int n_in,
                              void* d_out, int out_size) {
    const int*   src = (const int*)d_in[0];
    const int*   dst = (const int*)d_in[1];
    const float* h   = (const float*)d_in[2];
    const float* W1  = (const float*)d_in[3];
    const float* b1  = (const float*)d_in[4];
    const float* W2  = (const float*)d_in[5];
    const float* b2  = (const float*)d_in[6];
    float* out = (float*)d_out;

    const int E       = in_sizes[0];
    const int n_nodes = in_sizes[2] / IN_FEATS;

    int dev = 0, sms = 148;
    cudaGetDevice(&dev);
    cudaDeviceGetAttribute(&sms, cudaDevAttrMultiProcessorCount, dev);

    // Phase 1: node-level GEMM (persistent), b1 folded into P
    cudaFuncSetAttribute(pq_gemm_kernel, cudaFuncAttributeMaxDynamicSharedMemorySize, SM_TOTAL);
    int n_tiles = (n_nodes + NTILE - 1) / NTILE;
    int grid1 = (n_tiles < sms) ? n_tiles : sms;
    pq_gemm_kernel<<<grid1, 256, SM_TOTAL>>>(h, W1, b1, n_nodes, n_tiles);

    // Phase 2: edge scoring, 4 edges per warp
    int grid2 = sms * 8;
    edge_score_kernel<<<grid2, 256>>>(src, dst, W2, b2, out, E);
}

// round 9
// speedup vs baseline: 3.9650x; 1.1206x over previous
#include <cuda_runtime.h>
#include <cuda_fp16.h>
#include <cstdint>

#define IN_FEATS   128
#define HIDDEN     128
#define MAX_NODES  100000
#define NTILE      64            // node rows per GEMM tile
#define BSTR_H     136           // SMEM row stride in halfs (272 B, conflict-free ldmatrix)

// P'|Q per node: 256 halfs = 512 B.  [P+b1 (128) | Q (128)]
__device__ __align__(16) __half g_pq[MAX_NODES * 256];

__device__ __forceinline__ uint32_t smem_u32(const void* p) {
    uint32_t a;
    asm("{ .reg .u64 t; cvta.to.shared.u64 t, %1; cvt.u32.u64 %0, t; }" : "=r"(a) : "l"(p));
    return a;
}

#define LDMATRIX_X4(r0, r1, r2, r3, addr) \
    asm volatile("ldmatrix.sync.aligned.m8n8.x4.shared.b16 {%0,%1,%2,%3}, [%4];" \
                 : "=r"(r0), "=r"(r1), "=r"(r2), "=r"(r3) : "r"(addr))

#define MMA16816(c0, c1, c2, c3, a0, a1, a2, a3, b0, b1) \
    asm volatile("mma.sync.aligned.m16n8k16.row.col.f32.f16.f16.f32 " \
                 "{%0,%1,%2,%3}, {%4,%5,%6,%7}, {%8,%9}, {%0,%1,%2,%3};" \
                 : "+f"(c0), "+f"(c1), "+f"(c2), "+f"(c3) \
                 : "r"(a0), "r"(a1), "r"(a2), "r"(a3), "r"(b0), "r"(b1))

// ---------------- SMEM layout for split-N GEMM ----------------
#define SM_B      0                               // 128 rows x 136 halfs = 34816 B
#define SM_A      (128 * BSTR_H * 2)              // 64 rows x 136 halfs = 17408 B
#define SM_B1S    (SM_A + NTILE * BSTR_H * 2)     // 128 f32 bias1
#define SM_TOTAL  (SM_B1S + 512)                  // 52736 B -> 2 CTAs/SM

// =====================================================================
// Phase 1 (split-N): CTA owns one 128-col half of PQ.
//   nh=0: P' = h @ W1[:, :128]^T + b1      (cols 0..127 of g_pq row)
//   nh=1: Q  = h @ W1[:, 128:]^T           (cols 128..255)
// Persistent over M tiles; 2 CTAs per SM.
// =====================================================================
__global__ void __launch_bounds__(256, 2)
pq_gemm_kernel(const float* __restrict__ h, const float* __restrict__ W1,
               const float* __restrict__ b1, int n_nodes, int n_tiles)
{
    extern __shared__ char smem[];
    const int tid = threadIdx.x;
    const int wid = tid >> 5;
    const int lid = tid & 31;
    const uint32_t sb = smem_u32(smem);

    const int nh = blockIdx.x & 1;                // which output half
    const int kof = nh * 128;

    if (tid < 128) reinterpret_cast<float*>(smem + SM_B1S)[tid] = b1[tid];

    // ---- Load + convert this half's B (W1) into SMEM once: 128 rows x 128 halfs ----
    {
        #pragma unroll
        for (int i = 0; i < 16; i++) {
            int idx = tid + i * 256;              // 4096 float4 total
            int n2 = idx >> 5;                    // output col 0..127 (within half)
            int k  = (idx & 31) * 4;
            float4 v = *reinterpret_cast<const float4*>(W1 + n2 * 256 + kof + k);
            __half2* dp = reinterpret_cast<__half2*>(smem + SM_B + (n2 * BSTR_H + k) * 2);
            dp[0] = __floats2half2_rn(v.x, v.y);
            dp[1] = __floats2half2_rn(v.z, v.w);
        }
    }

    const int tstride = gridDim.x >> 1;
    int t = blockIdx.x >> 1;
    if (t >= n_tiles) return;

    // A-register prefetch: 8 float4 per thread = one 64x128 f32 tile
    float4 areg[8];
    auto load_a = [&](int tt) {
        #pragma unroll
        for (int i = 0; i < 8; i++) {
            int idx = tid + i * 256;
            int row = idx >> 5;
            int k   = (idx & 31) * 4;
            int grow = tt * NTILE + row;
            if (grow >= n_nodes) grow = 0;        // clamp (values unused)
            areg[i] = *reinterpret_cast<const float4*>(h + (size_t)grow * IN_FEATS + k);
        }
    };
    load_a(t);

    const int wm = wid >> 2;                      // 0..1 : rows wm*32
    const int wn = wid & 3;                       // 0..3 : cols wn*32 (within half)
    const int lr = lid & 15;
    const int lc = (lid >> 4) * 8;
    const int g8  = lid >> 2;
    const int tig = lid & 3;

    const uint32_t b_lane = sb + SM_B + (uint32_t)(wn * 32 + lr) * (BSTR_H * 2) + (uint32_t)lc * 2;
    const uint32_t a_lane = sb + SM_A + (uint32_t)(wm * 32 + lr) * (BSTR_H * 2) + (uint32_t)lc * 2;
    const float* b1s = reinterpret_cast<const float*>(smem + SM_B1S);
    const bool is_p = (nh == 0);

    for (; t < n_tiles; t += tstride) {
        // convert prefetched A regs into SMEM fp16
        #pragma unroll
        for (int i = 0; i < 8; i++) {
            int idx = tid + i * 256;
            int row = idx >> 5;
            int k   = (idx & 31) * 4;
            __half2* dp = reinterpret_cast<__half2*>(smem + SM_A + (row * BSTR_H + k) * 2);
            dp[0] = __floats2half2_rn(areg[i].x, areg[i].y);
            dp[1] = __floats2half2_rn(areg[i].z, areg[i].w);
        }
        __syncthreads();

        int tn = t + tstride;
        if (tn < n_tiles) load_a(tn);             // hidden under MMA

        float acc[2][4][4];
        #pragma unroll
        for (int mt = 0; mt < 2; mt++)
            #pragma unroll
            for (int nt = 0; nt < 4; nt++)
                #pragma unroll
                for (int c = 0; c < 4; c++) acc[mt][nt][c] = 0.f;

        #pragma unroll
        for (int ks = 0; ks < 8; ks++) {
            const uint32_t koff = (uint32_t)ks * 32;
            uint32_t a[2][4];
            #pragma unroll
            for (int mt = 0; mt < 2; mt++)
                LDMATRIX_X4(a[mt][0], a[mt][1], a[mt][2], a[mt][3],
                            a_lane + (uint32_t)(mt * 16 * BSTR_H * 2) + koff);
            uint32_t bf[2][4];
            #pragma unroll
            for (int ntp = 0; ntp < 2; ntp++)
                LDMATRIX_X4(bf[ntp][0], bf[ntp][1], bf[ntp][2], bf[ntp][3],
                            b_lane + (uint32_t)(ntp * 16 * BSTR_H * 2) + koff);
            #pragma unroll
            for (int mt = 0; mt < 2; mt++) {
                #pragma unroll
                for (int ntp = 0; ntp < 2; ntp++) {
                    MMA16816(acc[mt][2*ntp][0], acc[mt][2*ntp][1], acc[mt][2*ntp][2], acc[mt][2*ntp][3],
                             a[mt][0], a[mt][1], a[mt][2], a[mt][3], bf[ntp][0], bf[ntp][2]);
                    MMA16816(acc[mt][2*ntp+1][0], acc[mt][2*ntp+1][1], acc[mt][2*ntp+1][2], acc[mt][2*ntp+1][3],
                             a[mt][0], a[mt][1], a[mt][2], a[mt][3], bf[ntp][1], bf[ntp][3]);
                }
            }
        }

        // epilogue: (+b1 if P half), fp16 store to g_pq
        #pragma unroll
        for (int mt = 0; mt < 2; mt++) {
            #pragma unroll
            for (int hh = 0; hh < 2; hh++) {
                int grow = t * NTILE + wm * 32 + mt * 16 + g8 + hh * 8;
                if (grow < n_nodes) {
                    #pragma unroll
                    for (int nt = 0; nt < 4; nt++) {
                        int col = wn * 32 + nt * 8 + tig * 2;
                        float v0 = acc[mt][nt][hh * 2 + 0];
                        float v1 = acc[mt][nt][hh * 2 + 1];
                        if (is_p) { v0 += b1s[col]; v1 += b1s[col + 1]; }
                        __half2 hv = __floats2half2_rn(v0, v1);
                        *reinterpret_cast<__half2*>(g_pq + (size_t)grow * 256 + nh * 128 + col) = hv;
                    }
                }
            }
        }
        __syncthreads();   // all LDSM reads of A done before next tile's STS
    }
}

// =====================================================================
// Phase 2: per-edge score. 8 lanes per edge, 2 edges per octet-group per
// iteration (8 edges per warp) for load-level parallelism.
// =====================================================================
__device__ __forceinline__ float dot8(uint4 p, uint4 q, float4 w0, float4 w1) {
    const __half2 z = __float2half2_rn(0.f);
    __half2 h0 = __hmax2(__hadd2(*reinterpret_cast<__half2*>(&p.x),
                                 *reinterpret_cast<__half2*>(&q.x)), z);
    __half2 h1 = __hmax2(__hadd2(*reinterpret_cast<__half2*>(&p.y),
                                 *reinterpret_cast<__half2*>(&q.y)), z);
    __half2 h2 = __hmax2(__hadd2(*reinterpret_cast<__half2*>(&p.z),
                                 *reinterpret_cast<__half2*>(&q.z)), z);
    __half2 h3 = __hmax2(__hadd2(*reinterpret_cast<__half2*>(&p.w),
                                 *reinterpret_cast<__half2*>(&q.w)), z);
    float2 f0 = __half22float2(h0);
    float2 f1 = __half22float2(h1);
    float2 f2 = __half22float2(h2);
    float2 f3 = __half22float2(h3);
    float a = f0.x * w0.x;
    a = fmaf(f0.y, w0.y, a);
    a = fmaf(f1.x, w0.z, a);
    a = fmaf(f1.y, w0.w, a);
    a = fmaf(f2.x, w1.x, a);
    a = fmaf(f2.y, w1.y, a);
    a = fmaf(f3.x, w1.z, a);
    a = fmaf(f3.y, w1.w, a);
    return a;
}

__global__ void __launch_bounds__(256)
edge_score_kernel(const int* __restrict__ src, const int* __restrict__ dst,
                  const float* __restrict__ W2, const float* __restrict__ b2,
                  float* __restrict__ out, int E)
{
    const int lane = threadIdx.x & 31;
    const int oct  = lane & 7;           // dim octet within edge
    const int sub  = lane >> 3;          // edge slot within warp (0..3)
    const int warp_gid = (blockIdx.x * blockDim.x + threadIdx.x) >> 5;
    const int nwarps = (gridDim.x * blockDim.x) >> 5;

    const float4 w2a0 = *reinterpret_cast<const float4*>(W2 + oct * 8);
    const float4 w2a1 = *reinterpret_cast<const float4*>(W2 + oct * 8 + 4);
    const float4 w2b0 = *reinterpret_cast<const float4*>(W2 + 64 + oct * 8);
    const float4 w2b1 = *reinterpret_cast<const float4*>(W2 + 64 + oct * 8 + 4);
    const float bias2 = b2[0];
    const char* pqb = reinterpret_cast<const char*>(g_pq);

    for (int base = warp_gid * 8; base < E; base += nwarps * 8) {
        int e0 = base + sub;
        int e1 = base + 4 + sub;
        bool v0 = e0 < E, v1 = e1 < E;
        int i0 = v0 ? e0 : (E - 1);
        int i1 = v1 ? e1 : (E - 1);
        int s0 = __ldg(src + i0), d0 = __ldg(dst + i0);
        int s1 = __ldg(src + i1), d1 = __ldg(dst + i1);

        const char* p0 = pqb + (size_t)s0 * 512;
        const char* q0 = pqb + (size_t)d0 * 512 + 256;
        const char* p1 = pqb + (size_t)s1 * 512;
        const char* q1 = pqb + (size_t)d1 * 512 + 256;

        // 8 independent 16B loads in flight
        uint4 pa0 = *reinterpret_cast<const uint4*>(p0 + oct * 16);
        uint4 pb0 = *reinterpret_cast<const uint4*>(p0 + 128 + oct * 16);
        uint4 qa0 = *reinterpret_cast<const uint4*>(q0 + oct * 16);
        uint4 qb0 = *reinterpret_cast<const uint4*>(q0 + 128 + oct * 16);
        uint4 pa1 = *reinterpret_cast<const uint4*>(p1 + oct * 16);
        uint4 pb1 = *reinterpret_cast<const uint4*>(p1 + 128 + oct * 16);
        uint4 qa1 = *reinterpret_cast<const uint4*>(q1 + oct * 16);
        uint4 qb1 = *reinterpret_cast<const uint4*>(q1 + 128 + oct * 16);

        float acc0 = dot8(pa0, qa0, w2a0, w2a1) + dot8(pb0, qb0, w2b0, w2b1);
        float acc1 = dot8(pa1, qa1, w2a0, w2a1) + dot8(pb1, qb1, w2b0, w2b1);

        acc0 += __shfl_xor_sync(0xFFFFFFFF, acc0, 1);
        acc1 += __shfl_xor_sync(0xFFFFFFFF, acc1, 1);
        acc0 += __shfl_xor_sync(0xFFFFFFFF, acc0, 2);
        acc1 += __shfl_xor_sync(0xFFFFFFFF, acc1, 2);
        acc0 += __shfl_xor_sync(0xFFFFFFFF, acc0, 4);
        acc1 += __shfl_xor_sync(0xFFFFFFFF, acc1, 4);

        if (oct == 0) {
            if (v0) out[e0] = 1.f / (1.f + __expf(-(acc0 + bias2)));
            if (v1) out[e1] = 1.f / (1.f + __expf(-(acc1 + bias2)));
        }
    }
}

// ---------------- Launch ----------------
extern "C" void kernel_launch(void* const* d_in, const int* in_sizes, int n_in,
                              void* d_out, int out_size) {
    const int*   src = (const int*)d_in[0];
    const int*   dst = (const int*)d_in[1];
    const float* h   = (const float*)d_in[2];
    const float* W1  = (const float*)d_in[3];
    const float* b1  = (const float*)d_in[4];
    const float* W2  = (const float*)d_in[5];
    const float* b2  = (const float*)d_in[6];
    float* out = (float*)d_out;

    const int E       = in_sizes[0];
    const int n_nodes = in_sizes[2] / IN_FEATS;

    int dev = 0, sms = 148;
    cudaGetDevice(&dev);
    cudaDeviceGetAttribute(&sms, cudaDevAttrMultiProcessorCount, dev);

    // Phase 1: split-N node GEMM, 2 CTAs per SM (P-half and Q-half interleaved)
    cudaFuncSetAttribute(pq_gemm_kernel, cudaFuncAttributeMaxDynamicSharedMemorySize, SM_TOTAL);
    int n_tiles = (n_nodes + NTILE - 1) / NTILE;
    int grid1 = 2 * ((n_tiles < sms) ? n_tiles : sms);
    pq_gemm_kernel<<<grid1, 256, SM_TOTAL>>>(h, W1, b1, n_nodes, n_tiles);

    // Phase 2: edge scoring, 8 edges per warp (2 per octet-group)
    int grid2 = sms * 8;
    edge_score_kernel<<<grid2, 256>>>(src, dst, W2, b2, out, E);
}